// round 17
// baseline (speedup 1.0000x reference)
#include <cuda_runtime.h>
#include <math.h>

// RegionalAttentionPool: B=16, N=4096, D=512, R=64, K=128
// Single fused kernel: one CTA per (b,r), 4 warps x 32 k's each, processed
// TWO ROWS PER ITERATION: 8 independent LDG.128 in flight, two interleaved
// dot chains and shuffle butterflies share one latency round-trip.
// Warp holds both rows in registers; score via 5-shuffle butterfly;
// accumulate e = exp(score+bias) unnormalized (scores ~ N(0,1): no overflow,
// no max pass; warp partials merge by plain addition).
// __launch_bounds__(128, 6): <=85 regs -> 6 CTAs/SM, matching the 6.9
// CTAs/SM the 1024-CTA grid offers (full duty, no ragged wave).

constexpr int Bc = 16;
constexpr int Nc = 4096;
constexpr int Dc = 512;
constexpr int Rc = 64;
constexpr int Kc = 128;
constexpr int D4 = Dc / 4;          // 128 float4 per row

__global__ __launch_bounds__(128, 6)
void fused_regional_pool(const float4* __restrict__ x4,
                         const int*    __restrict__ ridx,
                         const float4* __restrict__ W4,
                         const float*  __restrict__ bias,
                         float4*       __restrict__ out4)
{
    __shared__ int    s_idx[Kc];
    __shared__ float  s_l[4];
    __shared__ float4 s_acc[3][128];     // warp 1..3 partial accumulators

    const int tid  = threadIdx.x;        // 0..127
    const int lane = tid & 31;
    const int warp = tid >> 5;           // 0..3
    const int r    = blockIdx.x % Rc;
    const int b    = blockIdx.x / Rc;

    if (tid < Kc) s_idx[tid] = __ldg(&ridx[r * Kc + tid]);

    // W resident in registers (lane covers d = 4*(j*32+lane) .. +3)
    float4 wv[4];
    #pragma unroll
    for (int j = 0; j < 4; j++) wv[j] = W4[j * 32 + lane];
    const float b0 = bias[0];

    __syncthreads();

    const float4* __restrict__ xb = x4 + (size_t)b * (Nc * D4);

    float  l = 0.0f;
    float4 acc0 = make_float4(0.f, 0.f, 0.f, 0.f);
    float4 acc1 = make_float4(0.f, 0.f, 0.f, 0.f);
    float4 acc2 = make_float4(0.f, 0.f, 0.f, 0.f);
    float4 acc3 = make_float4(0.f, 0.f, 0.f, 0.f);

    // each warp: 32 rows, two per iteration (8 loads in flight, interleaved
    // dot chains + shuffle butterflies share one latency round-trip)
    #pragma unroll 1
    for (int i = 0; i < 32; i += 2) {
        const float4* __restrict__ rowA = xb + (size_t)s_idx[warp * 32 + i    ] * D4;
        const float4* __restrict__ rowB = xb + (size_t)s_idx[warp * 32 + i + 1] * D4;

        float4 a0 = rowA[      lane];
        float4 a1 = rowA[ 32 + lane];
        float4 a2 = rowA[ 64 + lane];
        float4 a3 = rowA[ 96 + lane];
        float4 c0 = rowB[      lane];
        float4 c1 = rowB[ 32 + lane];
        float4 c2 = rowB[ 64 + lane];
        float4 c3 = rowB[ 96 + lane];

        // four independent 8-FFMA chains (two per row)
        float dA1, dA2, dB1, dB2;
        dA1  = a0.x * wv[0].x;
        dA2  = a2.x * wv[2].x;
        dB1  = c0.x * wv[0].x;
        dB2  = c2.x * wv[2].x;
        dA1 = fmaf(a0.y, wv[0].y, dA1);
        dA2 = fmaf(a2.y, wv[2].y, dA2);
        dB1 = fmaf(c0.y, wv[0].y, dB1);
        dB2 = fmaf(c2.y, wv[2].y, dB2);
        dA1 = fmaf(a0.z, wv[0].z, dA1);
        dA2 = fmaf(a2.z, wv[2].z, dA2);
        dB1 = fmaf(c0.z, wv[0].z, dB1);
        dB2 = fmaf(c2.z, wv[2].z, dB2);
        dA1 = fmaf(a0.w, wv[0].w, dA1);
        dA2 = fmaf(a2.w, wv[2].w, dA2);
        dB1 = fmaf(c0.w, wv[0].w, dB1);
        dB2 = fmaf(c2.w, wv[2].w, dB2);
        dA1 = fmaf(a1.x, wv[1].x, dA1);
        dA2 = fmaf(a3.x, wv[3].x, dA2);
        dB1 = fmaf(c1.x, wv[1].x, dB1);
        dB2 = fmaf(c3.x, wv[3].x, dB2);
        dA1 = fmaf(a1.y, wv[1].y, dA1);
        dA2 = fmaf(a3.y, wv[3].y, dA2);
        dB1 = fmaf(c1.y, wv[1].y, dB1);
        dB2 = fmaf(c3.y, wv[3].y, dB2);
        dA1 = fmaf(a1.z, wv[1].z, dA1);
        dA2 = fmaf(a3.z, wv[3].z, dA2);
        dB1 = fmaf(c1.z, wv[1].z, dB1);
        dB2 = fmaf(c3.z, wv[3].z, dB2);
        dA1 = fmaf(a1.w, wv[1].w, dA1);
        dA2 = fmaf(a3.w, wv[3].w, dA2);
        dB1 = fmaf(c1.w, wv[1].w, dB1);
        dB2 = fmaf(c3.w, wv[3].w, dB2);
        float dotA = dA1 + dA2;
        float dotB = dB1 + dB2;

        // two interleaved 5-stage butterflies (throughput-limited, not 2x latency)
        #pragma unroll
        for (int off = 16; off > 0; off >>= 1) {
            dotA += __shfl_xor_sync(0xffffffffu, dotA, off);
            dotB += __shfl_xor_sync(0xffffffffu, dotB, off);
        }

        const float eA = __expf(dotA + b0);
        const float eB = __expf(dotB + b0);
        l += eA + eB;

        acc0.x = fmaf(eA, a0.x, acc0.x);
        acc0.y = fmaf(eA, a0.y, acc0.y);
        acc0.z = fmaf(eA, a0.z, acc0.z);
        acc0.w = fmaf(eA, a0.w, acc0.w);
        acc1.x = fmaf(eA, a1.x, acc1.x);
        acc1.y = fmaf(eA, a1.y, acc1.y);
        acc1.z = fmaf(eA, a1.z, acc1.z);
        acc1.w = fmaf(eA, a1.w, acc1.w);
        acc2.x = fmaf(eA, a2.x, acc2.x);
        acc2.y = fmaf(eA, a2.y, acc2.y);
        acc2.z = fmaf(eA, a2.z, acc2.z);
        acc2.w = fmaf(eA, a2.w, acc2.w);
        acc3.x = fmaf(eA, a3.x, acc3.x);
        acc3.y = fmaf(eA, a3.y, acc3.y);
        acc3.z = fmaf(eA, a3.z, acc3.z);
        acc3.w = fmaf(eA, a3.w, acc3.w);

        acc0.x = fmaf(eB, c0.x, acc0.x);
        acc0.y = fmaf(eB, c0.y, acc0.y);
        acc0.z = fmaf(eB, c0.z, acc0.z);
        acc0.w = fmaf(eB, c0.w, acc0.w);
        acc1.x = fmaf(eB, c1.x, acc1.x);
        acc1.y = fmaf(eB, c1.y, acc1.y);
        acc1.z = fmaf(eB, c1.z, acc1.z);
        acc1.w = fmaf(eB, c1.w, acc1.w);
        acc2.x = fmaf(eB, c2.x, acc2.x);
        acc2.y = fmaf(eB, c2.y, acc2.y);
        acc2.z = fmaf(eB, c2.z, acc2.z);
        acc2.w = fmaf(eB, c2.w, acc2.w);
        acc3.x = fmaf(eB, c3.x, acc3.x);
        acc3.y = fmaf(eB, c3.y, acc3.y);
        acc3.z = fmaf(eB, c3.z, acc3.z);
        acc3.w = fmaf(eB, c3.w, acc3.w);
    }

    // merge the 4 warp partials (plain sums -- no rescale needed)
    if (warp > 0) {
        s_acc[warp - 1][  0 + lane] = acc0;
        s_acc[warp - 1][ 32 + lane] = acc1;
        s_acc[warp - 1][ 64 + lane] = acc2;
        s_acc[warp - 1][ 96 + lane] = acc3;
    }
    if (lane == 0) s_l[warp] = l;
    __syncthreads();

    if (warp == 0) {
        const float ltot = (l + s_l[1]) + (s_l[2] + s_l[3]);
        const float inv  = 1.0f / ltot;

        #pragma unroll
        for (int j = 0; j < 4; j++) {
            float4 a = (j == 0) ? acc0 : (j == 1) ? acc1 : (j == 2) ? acc2 : acc3;
            float4 t0 = s_acc[0][j * 32 + lane];
            float4 t1 = s_acc[1][j * 32 + lane];
            float4 t2 = s_acc[2][j * 32 + lane];
            a.x = (a.x + t0.x + t1.x + t2.x) * inv;
            a.y = (a.y + t0.y + t1.y + t2.y) * inv;
            a.z = (a.z + t0.z + t1.z + t2.z) * inv;
            a.w = (a.w + t0.w + t1.w + t2.w) * inv;
            out4[(size_t)blockIdx.x * D4 + j * 32 + lane] = a;
        }
    }
}

extern "C" void kernel_launch(void* const* d_in, const int* in_sizes, int n_in,
                              void* d_out, int out_size)
{
    const float4* x4   = (const float4*)d_in[0];   // (B, N, D) f32
    const int*    ridx = (const int*)   d_in[1];   // (R, K) i32
    const float4* W4   = (const float4*)d_in[2];   // (1, D) f32
    const float*  bias = (const float*) d_in[3];   // (1,) f32

    fused_regional_pool<<<Bc * Rc, 128>>>(x4, ridx, W4, bias, (float4*)d_out);
    (void)in_sizes; (void)n_in; (void)out_size;
}